// round 13
// baseline (speedup 1.0000x reference)
#include <cuda_runtime.h>
#include <cuda_fp16.h>
#include <math_constants.h>

#define N_NODES 50000
#define N_EDGES 1600000
#define ET      (N_EDGES + N_NODES)
#define EQ      (N_EDGES / 4)
#define HID     128
#define NG      512
#define SCAN_B  1024
#define NB      ((N_NODES + SCAN_B - 1) / SCAN_B)   // 49

// ---------------- scratch (device globals; allocation-free) ----------------
__device__ __half g_hh[(size_t)N_NODES * HID];
__device__ float g_agg[(size_t)N_NODES * HID];
__device__ float g_asrc[N_NODES];
__device__ float g_adst[N_NODES];
__device__ int   g_rowptr[N_NODES + 1];
__device__ int   g_cursor[N_NODES];
__device__ int   g_csrc[ET];
__device__ int   g_btot[NB];
__device__ float g_maxp[NG * HID];
__device__ float g_sump[NG * HID];
__device__ int   g_cnt[NG];
// global max of asrc per layer, stored as order-preserving int key.
// Statically initialized to key(-inf); atomicMax with deterministic values is
// idempotent across graph replays -> outputs identical every call.
__device__ int   g_lmax[2] = {(int)0x807FFFFF, (int)0x807FFFFF};

// order-preserving float<->int key (handles negatives)
__device__ __forceinline__ int fkey(float f) {
    int b = __float_as_int(f);
    return b >= 0 ? b : b ^ 0x7FFFFFFF;
}
__device__ __forceinline__ float funkey(int k) {
    return __int_as_float(k >= 0 ? k : k ^ 0x7FFFFFFF);
}

// ---------------- f32x2 packed helpers ----------------
__device__ __forceinline__ unsigned long long fma2(unsigned long long a,
                                                   unsigned long long b,
                                                   unsigned long long c) {
    unsigned long long d;
    asm("fma.rn.f32x2 %0, %1, %2, %3;" : "=l"(d) : "l"(a), "l"(b), "l"(c));
    return d;
}
__device__ __forceinline__ unsigned long long pack2(float lo, float hi) {
    unsigned long long r;
    asm("mov.b64 %0, {%1, %2};" : "=l"(r) : "f"(lo), "f"(hi));
    return r;
}
__device__ __forceinline__ void unpack2(unsigned long long v, float& lo, float& hi) {
    asm("mov.b64 {%0, %1}, %2;" : "=f"(lo), "=f"(hi) : "l"(v));
}

// ---------------- init ----------------
__global__ void init_kernel() {
    int i = blockIdx.x * blockDim.x + threadIdx.x;
    if (i < N_NODES) g_cursor[i] = 1;                 // self-loop pre-counted
    if (i < NG * HID) { g_maxp[i] = 0.f; g_sump[i] = 0.f; }
    if (i < NG) g_cnt[i] = 0;
}

// ---------------- histogram (x4 unroll, real edges only) -------------------
__global__ void hist_kernel(const int* __restrict__ ei) {
    int t = blockIdx.x * blockDim.x + threadIdx.x;
    if (t >= EQ) return;
    int4 d = *(const int4*)(ei + N_EDGES + t * 4);
    atomicAdd(&g_cursor[d.x], 1);
    atomicAdd(&g_cursor[d.y], 1);
    atomicAdd(&g_cursor[d.z], 1);
    atomicAdd(&g_cursor[d.w], 1);
}

// ---------------- hierarchical scan: 3 small kernels ----------------
__global__ __launch_bounds__(SCAN_B) void scan1_kernel() {
    __shared__ int sh[32];
    int b = blockIdx.x, t = threadIdx.x, lane = t & 31, wid = t >> 5;
    int idx = b * SCAN_B + t;
    int v = (idx < N_NODES) ? g_cursor[idx] : 0;
    int x = v;
#pragma unroll
    for (int o = 1; o < 32; o <<= 1) {
        int y = __shfl_up_sync(0xffffffffu, x, o);
        if (lane >= o) x += y;
    }
    if (lane == 31) sh[wid] = x;
    __syncthreads();
    if (wid == 0) {
        int y = sh[lane];
#pragma unroll
        for (int o = 1; o < 32; o <<= 1) {
            int z = __shfl_up_sync(0xffffffffu, y, o);
            if (lane >= o) y += z;
        }
        sh[lane] = y;
    }
    __syncthreads();
    int offs = wid ? sh[wid - 1] : 0;
    if (idx < N_NODES) g_rowptr[idx] = offs + x - v;
    if (t == SCAN_B - 1) g_btot[b] = offs + x;
}

__global__ void scan2_kernel() {
    __shared__ int wsum[2];
    int t = threadIdx.x, lane = t & 31, wid = t >> 5;
    int v = (t < NB) ? g_btot[t] : 0;
    int x = v;
#pragma unroll
    for (int o = 1; o < 32; o <<= 1) {
        int y = __shfl_up_sync(0xffffffffu, x, o);
        if (lane >= o) x += y;
    }
    if (lane == 31) wsum[wid] = x;
    __syncthreads();
    if (wid == 1) x += wsum[0];
    if (t < NB) g_btot[t] = x - v;
    if (t == NB - 1) g_rowptr[N_NODES] = x;
}

__global__ void scan3_kernel() {
    int i = blockIdx.x * blockDim.x + threadIdx.x;
    if (i < N_NODES) {
        int ex = g_rowptr[i] + g_btot[i / SCAN_B];
        g_rowptr[i] = ex;
        g_cursor[i] = ex;
    }
}

// ---------------- scatter (x4 unroll) + self-loop tail ----------------
__global__ void scatter_kernel(const int* __restrict__ ei) {
    int t = blockIdx.x * blockDim.x + threadIdx.x;
    if (t < EQ) {
        int4 s = *(const int4*)(ei + t * 4);
        int4 d = *(const int4*)(ei + N_EDGES + t * 4);
        int p0 = atomicAdd(&g_cursor[d.x], 1);
        int p1 = atomicAdd(&g_cursor[d.y], 1);
        int p2 = atomicAdd(&g_cursor[d.z], 1);
        int p3 = atomicAdd(&g_cursor[d.w], 1);
        g_csrc[p0] = s.x; g_csrc[p1] = s.y; g_csrc[p2] = s.z; g_csrc[p3] = s.w;
    } else {
        int v = t - EQ;
        if (v < N_NODES) {
            int p = atomicAdd(&g_cursor[v], 1);
            g_csrc[p] = v;
        }
    }
}

// -------- fused GEMM: h = relu(A)@W (fp16) + asrc/adst + global asrc max ---
__global__ __launch_bounds__(256, 2) void gemm_fused(const float* __restrict__ A_ext,
                                                     const float* __restrict__ W,
                                                     const float* __restrict__ av,
                                                     const float* __restrict__ adv,
                                                     int lx) {
    const float* __restrict__ A = A_ext ? A_ext : g_agg;
    __shared__ float As[128 * 36];
    __shared__ float Ws[32 * 132];
    __shared__ int smax;
    const int tid = threadIdx.x;
    const int row0 = blockIdx.x * 128;
    const int tx = tid & 15, ty = tid >> 4;

    unsigned long long acc2[8][4];
#pragma unroll
    for (int i = 0; i < 8; i++)
#pragma unroll
        for (int j = 0; j < 4; j++) acc2[i][j] = 0ull;

    for (int k0 = 0; k0 < 128; k0 += 32) {
#pragma unroll
        for (int i = 0; i < 4; i++) {
            int f = tid + i * 256;
            int r = f >> 3, kq = f & 7;
            int gr = row0 + r;
            float4 v = make_float4(0.f, 0.f, 0.f, 0.f);
            if (gr < N_NODES) v = *(const float4*)(A + (size_t)gr * HID + k0 + kq * 4);
            v.x = fmaxf(v.x, 0.f); v.y = fmaxf(v.y, 0.f);
            v.z = fmaxf(v.z, 0.f); v.w = fmaxf(v.w, 0.f);
            *(float4*)(&As[r * 36 + kq * 4]) = v;
        }
#pragma unroll
        for (int i = 0; i < 4; i++) {
            int f = tid + i * 256;
            int kk = f >> 5, cq = f & 31;
            float4 v = *(const float4*)(W + (size_t)(k0 + kk) * HID + cq * 4);
            *(float4*)(&Ws[kk * 132 + cq * 4]) = v;
        }
        __syncthreads();
#pragma unroll
        for (int k = 0; k < 32; k++) {
            float4 b0 = *(const float4*)(&Ws[k * 132 + tx * 4]);
            float4 b1 = *(const float4*)(&Ws[k * 132 + 64 + tx * 4]);
            unsigned long long bb[4];
            bb[0] = pack2(b0.x, b0.y); bb[1] = pack2(b0.z, b0.w);
            bb[2] = pack2(b1.x, b1.y); bb[3] = pack2(b1.z, b1.w);
#pragma unroll
            for (int i = 0; i < 8; i++) {
                float a = (i < 4) ? As[(ty * 4 + i) * 36 + k]
                                  : As[(64 + ty * 4 + (i - 4)) * 36 + k];
                unsigned long long aa = pack2(a, a);
#pragma unroll
                for (int j = 0; j < 4; j++) acc2[i][j] = fma2(aa, bb[j], acc2[i][j]);
            }
        }
        __syncthreads();
    }

    if (tid == 0) smax = (int)0x80000000;
    __syncthreads();

    float4 a1lo = *(const float4*)(av + tx * 4);
    float4 a1hi = *(const float4*)(av + 64 + tx * 4);
    float4 a2lo = *(const float4*)(adv + tx * 4);
    float4 a2hi = *(const float4*)(adv + 64 + tx * 4);
    const unsigned fullm = 0xffffffffu;
#pragma unroll
    for (int i = 0; i < 8; i++) {
        int gr = row0 + ((i < 4) ? (ty * 4 + i) : (64 + ty * 4 + (i - 4)));
        float c0, c1, c2, c3, c4, c5, c6, c7;
        unpack2(acc2[i][0], c0, c1); unpack2(acc2[i][1], c2, c3);
        unpack2(acc2[i][2], c4, c5); unpack2(acc2[i][3], c6, c7);
        float s1 = c0 * a1lo.x + c1 * a1lo.y + c2 * a1lo.z + c3 * a1lo.w
                 + c4 * a1hi.x + c5 * a1hi.y + c6 * a1hi.z + c7 * a1hi.w;
        float s2 = c0 * a2lo.x + c1 * a2lo.y + c2 * a2lo.z + c3 * a2lo.w
                 + c4 * a2hi.x + c5 * a2hi.y + c6 * a2hi.z + c7 * a2hi.w;
#pragma unroll
        for (int o = 8; o; o >>= 1) {
            s1 += __shfl_xor_sync(fullm, s1, o);
            s2 += __shfl_xor_sync(fullm, s2, o);
        }
        if (gr < N_NODES) {
            if (tx == 0) {
                g_asrc[gr] = s1;
                g_adst[gr] = s2;
                atomicMax(&smax, fkey(s1));
            }
            __half2 h0 = __floats2half2_rn(c0, c1);
            __half2 h1 = __floats2half2_rn(c2, c3);
            __half2 h2 = __floats2half2_rn(c4, c5);
            __half2 h3 = __floats2half2_rn(c6, c7);
            uint2 u0 = make_uint2(*(unsigned*)&h0, *(unsigned*)&h1);
            uint2 u1 = make_uint2(*(unsigned*)&h2, *(unsigned*)&h3);
            *(uint2*)(g_hh + (size_t)gr * HID + tx * 4)      = u0;
            *(uint2*)(g_hh + (size_t)gr * HID + 64 + tx * 4) = u1;
        }
    }
    __syncthreads();
    if (tid == 0) atomicMax(&g_lmax[lx], smax);
}

// ------ GAT aggregation: warp/node, SINGLE per-edge pass -------------------
// Uses global upper bound m = leaky(GMAX + adst) >= every incoming logit
// (leaky is monotone), so e = exp(l - m) <= 1 and softmax ratios are exact.
__global__ __launch_bounds__(256) void gat_agg_kernel(const float* __restrict__ bias,
                                                      const int* __restrict__ batch,
                                                      int pool_mode, int lx) {
    int w = (blockIdx.x * blockDim.x + threadIdx.x) >> 5;
    int lane = threadIdx.x & 31;
    if (w >= N_NODES) return;
    int beg = g_rowptr[w];
    int n = g_rowptr[w + 1] - beg;
    float ad = g_adst[w];
    float gmax = funkey(g_lmax[lx]);
    float mm = gmax + ad;
    float m = mm > 0.f ? mm : 0.2f * mm;   // = max possible incoming logit

    float ssum = 0.f;
    float4 acc = make_float4(0.f, 0.f, 0.f, 0.f);
    const int col = lane << 2;
    int i = 0;
    for (; i + 4 <= n; i += 4) {
        int s0 = g_csrc[beg + i + 0];
        int s1 = g_csrc[beg + i + 1];
        int s2 = g_csrc[beg + i + 2];
        int s3 = g_csrc[beg + i + 3];
        float a0 = g_asrc[s0], a1 = g_asrc[s1], a2 = g_asrc[s2], a3 = g_asrc[s3];
        uint2 u0 = *(const uint2*)(g_hh + (size_t)s0 * HID + col);
        uint2 u1 = *(const uint2*)(g_hh + (size_t)s1 * HID + col);
        uint2 u2 = *(const uint2*)(g_hh + (size_t)s2 * HID + col);
        uint2 u3 = *(const uint2*)(g_hh + (size_t)s3 * HID + col);
        float l0 = a0 + ad; l0 = l0 > 0.f ? l0 : 0.2f * l0;
        float l1 = a1 + ad; l1 = l1 > 0.f ? l1 : 0.2f * l1;
        float l2 = a2 + ad; l2 = l2 > 0.f ? l2 : 0.2f * l2;
        float l3 = a3 + ad; l3 = l3 > 0.f ? l3 : 0.2f * l3;
        float e0 = __expf(l0 - m), e1 = __expf(l1 - m);
        float e2 = __expf(l2 - m), e3 = __expf(l3 - m);
        ssum += (e0 + e1) + (e2 + e3);
        float2 f0a = __half22float2(*(__half2*)&u0.x), f0b = __half22float2(*(__half2*)&u0.y);
        float2 f1a = __half22float2(*(__half2*)&u1.x), f1b = __half22float2(*(__half2*)&u1.y);
        float2 f2a = __half22float2(*(__half2*)&u2.x), f2b = __half22float2(*(__half2*)&u2.y);
        float2 f3a = __half22float2(*(__half2*)&u3.x), f3b = __half22float2(*(__half2*)&u3.y);
        acc.x = fmaf(e0, f0a.x, acc.x); acc.y = fmaf(e0, f0a.y, acc.y);
        acc.z = fmaf(e0, f0b.x, acc.z); acc.w = fmaf(e0, f0b.y, acc.w);
        acc.x = fmaf(e1, f1a.x, acc.x); acc.y = fmaf(e1, f1a.y, acc.y);
        acc.z = fmaf(e1, f1b.x, acc.z); acc.w = fmaf(e1, f1b.y, acc.w);
        acc.x = fmaf(e2, f2a.x, acc.x); acc.y = fmaf(e2, f2a.y, acc.y);
        acc.z = fmaf(e2, f2b.x, acc.z); acc.w = fmaf(e2, f2b.y, acc.w);
        acc.x = fmaf(e3, f3a.x, acc.x); acc.y = fmaf(e3, f3a.y, acc.y);
        acc.z = fmaf(e3, f3b.x, acc.z); acc.w = fmaf(e3, f3b.y, acc.w);
    }
    for (; i < n; i++) {
        int s = g_csrc[beg + i];
        float a = g_asrc[s];
        uint2 u = *(const uint2*)(g_hh + (size_t)s * HID + col);
        float l = a + ad; l = l > 0.f ? l : 0.2f * l;
        float e = __expf(l - m);
        ssum += e;
        float2 fa = __half22float2(*(__half2*)&u.x);
        float2 fb = __half22float2(*(__half2*)&u.y);
        acc.x = fmaf(e, fa.x, acc.x); acc.y = fmaf(e, fa.y, acc.y);
        acc.z = fmaf(e, fb.x, acc.z); acc.w = fmaf(e, fb.y, acc.w);
    }
    float inv = 1.f / ssum;
    float4 bv = *(const float4*)(bias + col);
    acc.x = fmaf(acc.x, inv, bv.x);
    acc.y = fmaf(acc.y, inv, bv.y);
    acc.z = fmaf(acc.z, inv, bv.z);
    acc.w = fmaf(acc.w, inv, bv.w);

    if (!pool_mode) {
        *(float4*)(&g_agg[(size_t)w * HID + col]) = acc;
    } else {
        acc.x = fmaxf(acc.x, 0.f); acc.y = fmaxf(acc.y, 0.f);
        acc.z = fmaxf(acc.z, 0.f); acc.w = fmaxf(acc.w, 0.f);
        int g = batch[w];
        int base = g * HID + col;
        atomicMax((int*)&g_maxp[base + 0], __float_as_int(acc.x));
        atomicMax((int*)&g_maxp[base + 1], __float_as_int(acc.y));
        atomicMax((int*)&g_maxp[base + 2], __float_as_int(acc.z));
        atomicMax((int*)&g_maxp[base + 3], __float_as_int(acc.w));
        atomicAdd(&g_sump[base + 0], acc.x);
        atomicAdd(&g_sump[base + 1], acc.y);
        atomicAdd(&g_sump[base + 2], acc.z);
        atomicAdd(&g_sump[base + 3], acc.w);
        if (lane == 0) atomicAdd(&g_cnt[g], 1);
    }
}

__global__ void final_kernel(const float* __restrict__ fcw, const float* __restrict__ fcb,
                             float* __restrict__ out) {
    int w = (blockIdx.x * blockDim.x + threadIdx.x) >> 5;
    int lane = threadIdx.x & 31;
    if (w >= NG) return;
    float4 mx = *(const float4*)(&g_maxp[w * HID + (lane << 2)]);
    float4 sm = *(const float4*)(&g_sump[w * HID + (lane << 2)]);
    float4 w1 = *(const float4*)(fcw + (lane << 2));
    float4 w2 = *(const float4*)(fcw + HID + (lane << 2));
    float c = fmaxf((float)g_cnt[w], 1.f);
    float p = mx.x * w1.x + mx.y * w1.y + mx.z * w1.z + mx.w * w1.w
            + (sm.x * w2.x + sm.y * w2.y + sm.z * w2.z + sm.w * w2.w) / c;
#pragma unroll
    for (int o = 16; o; o >>= 1) p += __shfl_xor_sync(0xffffffffu, p, o);
    if (lane == 0) out[w] = p + fcb[0];
}

// ---------------- launch (CSR chain forked to overlap with GEMM1) ----------
extern "C" void kernel_launch(void* const* d_in, const int* in_sizes, int n_in,
                              void* d_out, int out_size) {
    const float* x   = (const float*)d_in[0];
    const int*   ei  = (const int*)d_in[1];
    const int*   bat = (const int*)d_in[2];
    const float* W1  = (const float*)d_in[3];
    const float* as1 = (const float*)d_in[4];
    const float* ad1 = (const float*)d_in[5];
    const float* b1  = (const float*)d_in[6];
    const float* W2  = (const float*)d_in[7];
    const float* as2 = (const float*)d_in[8];
    const float* ad2 = (const float*)d_in[9];
    const float* b2  = (const float*)d_in[10];
    const float* fcw = (const float*)d_in[11];
    const float* fcb = (const float*)d_in[12];
    float* out = (float*)d_out;

    const int TB = 256;
    const int initBlocks = (NG * HID + TB - 1) / TB;
    const int histBlocks = (EQ + TB - 1) / TB;
    const int scatBlocks = (EQ + N_NODES + TB - 1) / TB;
    const int nodeBlocks = (N_NODES + TB - 1) / TB;
    const int warpNodeBlocks = (N_NODES * 32 + TB - 1) / TB;
    const int gemmBlocks = (N_NODES + 127) / 128;

    cudaStream_t s2;
    cudaEvent_t ev0, ev1;
    cudaStreamCreateWithFlags(&s2, cudaStreamNonBlocking);
    cudaEventCreateWithFlags(&ev0, cudaEventDisableTiming);
    cudaEventCreateWithFlags(&ev1, cudaEventDisableTiming);

    cudaEventRecord(ev0, 0);
    cudaStreamWaitEvent(s2, ev0, 0);

    // main: GEMM1 — concurrent with CSR chain
    gemm_fused<<<gemmBlocks, TB>>>(x, W1, as1, ad1, 0);

    // s2: CSR build chain
    init_kernel<<<initBlocks, TB, 0, s2>>>();
    hist_kernel<<<histBlocks, TB, 0, s2>>>(ei);
    scan1_kernel<<<NB, SCAN_B, 0, s2>>>();
    scan2_kernel<<<1, 64, 0, s2>>>();
    scan3_kernel<<<nodeBlocks, TB, 0, s2>>>();
    scatter_kernel<<<scatBlocks, TB, 0, s2>>>(ei);
    cudaEventRecord(ev1, s2);

    cudaStreamWaitEvent(0, ev1, 0);                   // join

    gat_agg_kernel<<<warpNodeBlocks, TB>>>(b1, bat, 0, 0);
    gemm_fused<<<gemmBlocks, TB>>>(nullptr, W2, as2, ad2, 1);
    gat_agg_kernel<<<warpNodeBlocks, TB>>>(b2, bat, 1, 1);
    final_kernel<<<(NG * 32 + TB - 1) / TB, TB>>>(fcw, fcb, out);
}

// round 14
// speedup vs baseline: 1.1399x; 1.1399x over previous
#include <cuda_runtime.h>
#include <cuda_fp16.h>
#include <math_constants.h>

#define N_NODES 50000
#define N_EDGES 1600000
#define ET      (N_EDGES + N_NODES)
#define EQ      (N_EDGES / 4)
#define HID     128
#define NG      512
#define DEG_CAP 64
#define SCAN_B  1024
#define NB      ((N_NODES + SCAN_B - 1) / SCAN_B)   // 49

// ---------------- scratch (device globals; allocation-free) ----------------
__device__ __half g_hh[(size_t)N_NODES * HID];
__device__ float g_agg[(size_t)N_NODES * HID];
__device__ float g_asrc[N_NODES];
__device__ float g_adst[N_NODES];
__device__ int   g_rowptr[N_NODES + 1];
__device__ int   g_cursor[N_NODES];
__device__ int   g_csrc[ET];
__device__ int   g_btot[NB];
__device__ float g_maxp[NG * HID];
__device__ float g_sump[NG * HID];
__device__ int   g_cnt[NG];
// global max of asrc per layer (order-preserving int key). atomicMax with
// deterministic values is idempotent across graph replays.
__device__ int   g_lmax[2] = {(int)0x807FFFFF, (int)0x807FFFFF};

__device__ __forceinline__ int fkey(float f) {
    int b = __float_as_int(f);
    return b >= 0 ? b : b ^ 0x7FFFFFFF;
}
__device__ __forceinline__ float funkey(int k) {
    return __int_as_float(k >= 0 ? k : k ^ 0x7FFFFFFF);
}

// ---------------- f32x2 packed helpers ----------------
__device__ __forceinline__ unsigned long long fma2(unsigned long long a,
                                                   unsigned long long b,
                                                   unsigned long long c) {
    unsigned long long d;
    asm("fma.rn.f32x2 %0, %1, %2, %3;" : "=l"(d) : "l"(a), "l"(b), "l"(c));
    return d;
}
__device__ __forceinline__ unsigned long long pack2(float lo, float hi) {
    unsigned long long r;
    asm("mov.b64 %0, {%1, %2};" : "=l"(r) : "f"(lo), "f"(hi));
    return r;
}
__device__ __forceinline__ void unpack2(unsigned long long v, float& lo, float& hi) {
    asm("mov.b64 {%0, %1}, %2;" : "=f"(lo), "=f"(hi) : "l"(v));
}

// ---------------- init ----------------
__global__ void init_kernel() {
    int i = blockIdx.x * blockDim.x + threadIdx.x;
    if (i < N_NODES) g_cursor[i] = 1;                 // self-loop pre-counted
    if (i < NG * HID) { g_maxp[i] = 0.f; g_sump[i] = 0.f; }
    if (i < NG) g_cnt[i] = 0;
}

// ---------------- histogram (x4 unroll, real edges only) -------------------
__global__ void hist_kernel(const int* __restrict__ ei) {
    int t = blockIdx.x * blockDim.x + threadIdx.x;
    if (t >= EQ) return;
    int4 d = *(const int4*)(ei + N_EDGES + t * 4);
    atomicAdd(&g_cursor[d.x], 1);
    atomicAdd(&g_cursor[d.y], 1);
    atomicAdd(&g_cursor[d.z], 1);
    atomicAdd(&g_cursor[d.w], 1);
}

// ---------------- hierarchical scan: 3 small kernels ----------------
__global__ __launch_bounds__(SCAN_B) void scan1_kernel() {
    __shared__ int sh[32];
    int b = blockIdx.x, t = threadIdx.x, lane = t & 31, wid = t >> 5;
    int idx = b * SCAN_B + t;
    int v = (idx < N_NODES) ? g_cursor[idx] : 0;
    int x = v;
#pragma unroll
    for (int o = 1; o < 32; o <<= 1) {
        int y = __shfl_up_sync(0xffffffffu, x, o);
        if (lane >= o) x += y;
    }
    if (lane == 31) sh[wid] = x;
    __syncthreads();
    if (wid == 0) {
        int y = sh[lane];
#pragma unroll
        for (int o = 1; o < 32; o <<= 1) {
            int z = __shfl_up_sync(0xffffffffu, y, o);
            if (lane >= o) y += z;
        }
        sh[lane] = y;
    }
    __syncthreads();
    int offs = wid ? sh[wid - 1] : 0;
    if (idx < N_NODES) g_rowptr[idx] = offs + x - v;
    if (t == SCAN_B - 1) g_btot[b] = offs + x;
}

__global__ void scan2_kernel() {
    __shared__ int wsum[2];
    int t = threadIdx.x, lane = t & 31, wid = t >> 5;
    int v = (t < NB) ? g_btot[t] : 0;
    int x = v;
#pragma unroll
    for (int o = 1; o < 32; o <<= 1) {
        int y = __shfl_up_sync(0xffffffffu, x, o);
        if (lane >= o) x += y;
    }
    if (lane == 31) wsum[wid] = x;
    __syncthreads();
    if (wid == 1) x += wsum[0];
    if (t < NB) g_btot[t] = x - v;
    if (t == NB - 1) g_rowptr[N_NODES] = x;
}

__global__ void scan3_kernel() {
    int i = blockIdx.x * blockDim.x + threadIdx.x;
    if (i < N_NODES) {
        int ex = g_rowptr[i] + g_btot[i / SCAN_B];
        g_rowptr[i] = ex;
        g_cursor[i] = ex;
    }
}

// ---------------- scatter (x4 unroll) + self-loop tail ----------------
__global__ void scatter_kernel(const int* __restrict__ ei) {
    int t = blockIdx.x * blockDim.x + threadIdx.x;
    if (t < EQ) {
        int4 s = *(const int4*)(ei + t * 4);
        int4 d = *(const int4*)(ei + N_EDGES + t * 4);
        int p0 = atomicAdd(&g_cursor[d.x], 1);
        int p1 = atomicAdd(&g_cursor[d.y], 1);
        int p2 = atomicAdd(&g_cursor[d.z], 1);
        int p3 = atomicAdd(&g_cursor[d.w], 1);
        g_csrc[p0] = s.x; g_csrc[p1] = s.y; g_csrc[p2] = s.z; g_csrc[p3] = s.w;
    } else {
        int v = t - EQ;
        if (v < N_NODES) {
            int p = atomicAdd(&g_cursor[v], 1);
            g_csrc[p] = v;
        }
    }
}

// -------- fused GEMM: h = relu(A)@W (fp16) + asrc/adst + global asrc max ---
__global__ __launch_bounds__(256, 2) void gemm_fused(const float* __restrict__ A_ext,
                                                     const float* __restrict__ W,
                                                     const float* __restrict__ av,
                                                     const float* __restrict__ adv,
                                                     int lx) {
    const float* __restrict__ A = A_ext ? A_ext : g_agg;
    __shared__ float As[128 * 36];
    __shared__ float Ws[32 * 132];
    __shared__ int smax;
    const int tid = threadIdx.x;
    const int row0 = blockIdx.x * 128;
    const int tx = tid & 15, ty = tid >> 4;

    unsigned long long acc2[8][4];
#pragma unroll
    for (int i = 0; i < 8; i++)
#pragma unroll
        for (int j = 0; j < 4; j++) acc2[i][j] = 0ull;

    for (int k0 = 0; k0 < 128; k0 += 32) {
#pragma unroll
        for (int i = 0; i < 4; i++) {
            int f = tid + i * 256;
            int r = f >> 3, kq = f & 7;
            int gr = row0 + r;
            float4 v = make_float4(0.f, 0.f, 0.f, 0.f);
            if (gr < N_NODES) v = *(const float4*)(A + (size_t)gr * HID + k0 + kq * 4);
            v.x = fmaxf(v.x, 0.f); v.y = fmaxf(v.y, 0.f);
            v.z = fmaxf(v.z, 0.f); v.w = fmaxf(v.w, 0.f);
            *(float4*)(&As[r * 36 + kq * 4]) = v;
        }
#pragma unroll
        for (int i = 0; i < 4; i++) {
            int f = tid + i * 256;
            int kk = f >> 5, cq = f & 31;
            float4 v = *(const float4*)(W + (size_t)(k0 + kk) * HID + cq * 4);
            *(float4*)(&Ws[kk * 132 + cq * 4]) = v;
        }
        __syncthreads();
#pragma unroll
        for (int k = 0; k < 32; k++) {
            float4 b0 = *(const float4*)(&Ws[k * 132 + tx * 4]);
            float4 b1 = *(const float4*)(&Ws[k * 132 + 64 + tx * 4]);
            unsigned long long bb[4];
            bb[0] = pack2(b0.x, b0.y); bb[1] = pack2(b0.z, b0.w);
            bb[2] = pack2(b1.x, b1.y); bb[3] = pack2(b1.z, b1.w);
#pragma unroll
            for (int i = 0; i < 8; i++) {
                float a = (i < 4) ? As[(ty * 4 + i) * 36 + k]
                                  : As[(64 + ty * 4 + (i - 4)) * 36 + k];
                unsigned long long aa = pack2(a, a);
#pragma unroll
                for (int j = 0; j < 4; j++) acc2[i][j] = fma2(aa, bb[j], acc2[i][j]);
            }
        }
        __syncthreads();
    }

    if (tid == 0) smax = (int)0x80000000;
    __syncthreads();

    float4 a1lo = *(const float4*)(av + tx * 4);
    float4 a1hi = *(const float4*)(av + 64 + tx * 4);
    float4 a2lo = *(const float4*)(adv + tx * 4);
    float4 a2hi = *(const float4*)(adv + 64 + tx * 4);
    const unsigned fullm = 0xffffffffu;
#pragma unroll
    for (int i = 0; i < 8; i++) {
        int gr = row0 + ((i < 4) ? (ty * 4 + i) : (64 + ty * 4 + (i - 4)));
        float c0, c1, c2, c3, c4, c5, c6, c7;
        unpack2(acc2[i][0], c0, c1); unpack2(acc2[i][1], c2, c3);
        unpack2(acc2[i][2], c4, c5); unpack2(acc2[i][3], c6, c7);
        float s1 = c0 * a1lo.x + c1 * a1lo.y + c2 * a1lo.z + c3 * a1lo.w
                 + c4 * a1hi.x + c5 * a1hi.y + c6 * a1hi.z + c7 * a1hi.w;
        float s2 = c0 * a2lo.x + c1 * a2lo.y + c2 * a2lo.z + c3 * a2lo.w
                 + c4 * a2hi.x + c5 * a2hi.y + c6 * a2hi.z + c7 * a2hi.w;
#pragma unroll
        for (int o = 8; o; o >>= 1) {
            s1 += __shfl_xor_sync(fullm, s1, o);
            s2 += __shfl_xor_sync(fullm, s2, o);
        }
        if (gr < N_NODES) {
            if (tx == 0) {
                g_asrc[gr] = s1;
                g_adst[gr] = s2;
                atomicMax(&smax, fkey(s1));
            }
            __half2 h0 = __floats2half2_rn(c0, c1);
            __half2 h1 = __floats2half2_rn(c2, c3);
            __half2 h2 = __floats2half2_rn(c4, c5);
            __half2 h3 = __floats2half2_rn(c6, c7);
            uint2 u0 = make_uint2(*(unsigned*)&h0, *(unsigned*)&h1);
            uint2 u1 = make_uint2(*(unsigned*)&h2, *(unsigned*)&h3);
            *(uint2*)(g_hh + (size_t)gr * HID + tx * 4)      = u0;
            *(uint2*)(g_hh + (size_t)gr * HID + 64 + tx * 4) = u1;
        }
    }
    __syncthreads();
    if (tid == 0) atomicMax(&g_lmax[lx], smax);
}

// ------ GAT aggregation: warp/node; ONE lane-parallel weight pass ----------
// m = leaky(GMAX + adst) upper-bounds every incoming logit (leaky monotone),
// so e = exp(l - m) <= 1 and softmax ratios are exact. Pass A of the old
// 2-pass scheme (max computation) is eliminated; phase 2 unchanged (fastest
// measured form: shared-e broadcast + h gather, x4 scalar unroll).
__global__ __launch_bounds__(256) void gat_agg_kernel(const float* __restrict__ bias,
                                                      const int* __restrict__ batch,
                                                      int pool_mode, int lx) {
    __shared__ float shw[8][DEG_CAP];
    int w = (blockIdx.x * blockDim.x + threadIdx.x) >> 5;
    int lane = threadIdx.x & 31;
    int wid = (threadIdx.x >> 5) & 7;
    if (w >= N_NODES) return;
    int beg = g_rowptr[w];
    int n = g_rowptr[w + 1] - beg;
    float ad = g_adst[w];
    float mm = funkey(g_lmax[lx]) + ad;
    float m = mm > 0.f ? mm : 0.2f * mm;   // global upper bound on logits
    bool small = (n <= DEG_CAP);

    // single lane-parallel pass: e = exp(leaky(asrc+ad) - m), stash, sum
    float ssum = 0.f;
    for (int i = lane; i < n; i += 32) {
        int s = g_csrc[beg + i];
        float l = g_asrc[s] + ad;
        l = l > 0.f ? l : 0.2f * l;
        float e = __expf(l - m);
        ssum += e;
        if (small) shw[wid][i] = e;
    }
#pragma unroll
    for (int o = 16; o; o >>= 1) ssum += __shfl_xor_sync(0xffffffffu, ssum, o);
    float inv = 1.f / ssum;
    __syncwarp();

    // phase 2: gather Σ e * h[src]  (x4 scalar unroll — measured best)
    float4 acc = make_float4(0.f, 0.f, 0.f, 0.f);
    const int col = lane << 2;
    if (small) {
        int i = 0;
        for (; i + 4 <= n; i += 4) {
            int s0 = g_csrc[beg + i + 0];
            int s1 = g_csrc[beg + i + 1];
            int s2 = g_csrc[beg + i + 2];
            int s3 = g_csrc[beg + i + 3];
            float e0 = shw[wid][i + 0], e1 = shw[wid][i + 1];
            float e2 = shw[wid][i + 2], e3 = shw[wid][i + 3];
            uint2 u0 = *(const uint2*)(g_hh + (size_t)s0 * HID + col);
            uint2 u1 = *(const uint2*)(g_hh + (size_t)s1 * HID + col);
            uint2 u2 = *(const uint2*)(g_hh + (size_t)s2 * HID + col);
            uint2 u3 = *(const uint2*)(g_hh + (size_t)s3 * HID + col);
            float2 f0a = __half22float2(*(__half2*)&u0.x), f0b = __half22float2(*(__half2*)&u0.y);
            float2 f1a = __half22float2(*(__half2*)&u1.x), f1b = __half22float2(*(__half2*)&u1.y);
            float2 f2a = __half22float2(*(__half2*)&u2.x), f2b = __half22float2(*(__half2*)&u2.y);
            float2 f3a = __half22float2(*(__half2*)&u3.x), f3b = __half22float2(*(__half2*)&u3.y);
            acc.x = fmaf(e0, f0a.x, acc.x); acc.y = fmaf(e0, f0a.y, acc.y);
            acc.z = fmaf(e0, f0b.x, acc.z); acc.w = fmaf(e0, f0b.y, acc.w);
            acc.x = fmaf(e1, f1a.x, acc.x); acc.y = fmaf(e1, f1a.y, acc.y);
            acc.z = fmaf(e1, f1b.x, acc.z); acc.w = fmaf(e1, f1b.y, acc.w);
            acc.x = fmaf(e2, f2a.x, acc.x); acc.y = fmaf(e2, f2a.y, acc.y);
            acc.z = fmaf(e2, f2b.x, acc.z); acc.w = fmaf(e2, f2b.y, acc.w);
            acc.x = fmaf(e3, f3a.x, acc.x); acc.y = fmaf(e3, f3a.y, acc.y);
            acc.z = fmaf(e3, f3b.x, acc.z); acc.w = fmaf(e3, f3b.y, acc.w);
        }
        for (; i < n; i++) {
            int s = g_csrc[beg + i];
            float e = shw[wid][i];
            uint2 u = *(const uint2*)(g_hh + (size_t)s * HID + col);
            float2 fa = __half22float2(*(__half2*)&u.x);
            float2 fb = __half22float2(*(__half2*)&u.y);
            acc.x = fmaf(e, fa.x, acc.x); acc.y = fmaf(e, fa.y, acc.y);
            acc.z = fmaf(e, fb.x, acc.z); acc.w = fmaf(e, fb.y, acc.w);
        }
    } else {  // rare high-degree path: recompute e inline with global m
        for (int i = 0; i < n; i++) {
            int s = g_csrc[beg + i];
            float l = g_asrc[s] + ad;
            l = l > 0.f ? l : 0.2f * l;
            float e = __expf(l - m);
            uint2 u = *(const uint2*)(g_hh + (size_t)s * HID + col);
            float2 fa = __half22float2(*(__half2*)&u.x);
            float2 fb = __half22float2(*(__half2*)&u.y);
            acc.x = fmaf(e, fa.x, acc.x); acc.y = fmaf(e, fa.y, acc.y);
            acc.z = fmaf(e, fb.x, acc.z); acc.w = fmaf(e, fb.y, acc.w);
        }
    }
    float4 bv = *(const float4*)(bias + col);
    acc.x = fmaf(acc.x, inv, bv.x);
    acc.y = fmaf(acc.y, inv, bv.y);
    acc.z = fmaf(acc.z, inv, bv.z);
    acc.w = fmaf(acc.w, inv, bv.w);

    if (!pool_mode) {
        *(float4*)(&g_agg[(size_t)w * HID + col]) = acc;
    } else {
        acc.x = fmaxf(acc.x, 0.f); acc.y = fmaxf(acc.y, 0.f);
        acc.z = fmaxf(acc.z, 0.f); acc.w = fmaxf(acc.w, 0.f);
        int g = batch[w];
        int base = g * HID + col;
        atomicMax((int*)&g_maxp[base + 0], __float_as_int(acc.x));
        atomicMax((int*)&g_maxp[base + 1], __float_as_int(acc.y));
        atomicMax((int*)&g_maxp[base + 2], __float_as_int(acc.z));
        atomicMax((int*)&g_maxp[base + 3], __float_as_int(acc.w));
        atomicAdd(&g_sump[base + 0], acc.x);
        atomicAdd(&g_sump[base + 1], acc.y);
        atomicAdd(&g_sump[base + 2], acc.z);
        atomicAdd(&g_sump[base + 3], acc.w);
        if (lane == 0) atomicAdd(&g_cnt[g], 1);
    }
}

__global__ void final_kernel(const float* __restrict__ fcw, const float* __restrict__ fcb,
                             float* __restrict__ out) {
    int w = (blockIdx.x * blockDim.x + threadIdx.x) >> 5;
    int lane = threadIdx.x & 31;
    if (w >= NG) return;
    float4 mx = *(const float4*)(&g_maxp[w * HID + (lane << 2)]);
    float4 sm = *(const float4*)(&g_sump[w * HID + (lane << 2)]);
    float4 w1 = *(const float4*)(fcw + (lane << 2));
    float4 w2 = *(const float4*)(fcw + HID + (lane << 2));
    float c = fmaxf((float)g_cnt[w], 1.f);
    float p = mx.x * w1.x + mx.y * w1.y + mx.z * w1.z + mx.w * w1.w
            + (sm.x * w2.x + sm.y * w2.y + sm.z * w2.z + sm.w * w2.w) / c;
#pragma unroll
    for (int o = 16; o; o >>= 1) p += __shfl_xor_sync(0xffffffffu, p, o);
    if (lane == 0) out[w] = p + fcb[0];
}

// ---------------- launch (CSR chain forked to overlap with GEMM1) ----------
extern "C" void kernel_launch(void* const* d_in, const int* in_sizes, int n_in,
                              void* d_out, int out_size) {
    const float* x   = (const float*)d_in[0];
    const int*   ei  = (const int*)d_in[1];
    const int*   bat = (const int*)d_in[2];
    const float* W1  = (const float*)d_in[3];
    const float* as1 = (const float*)d_in[4];
    const float* ad1 = (const float*)d_in[5];
    const float* b1  = (const float*)d_in[6];
    const float* W2  = (const float*)d_in[7];
    const float* as2 = (const float*)d_in[8];
    const float* ad2 = (const float*)d_in[9];
    const float* b2  = (const float*)d_in[10];
    const float* fcw = (const float*)d_in[11];
    const float* fcb = (const float*)d_in[12];
    float* out = (float*)d_out;

    const int TB = 256;
    const int initBlocks = (NG * HID + TB - 1) / TB;
    const int histBlocks = (EQ + TB - 1) / TB;
    const int scatBlocks = (EQ + N_NODES + TB - 1) / TB;
    const int nodeBlocks = (N_NODES + TB - 1) / TB;
    const int warpNodeBlocks = (N_NODES * 32 + TB - 1) / TB;
    const int gemmBlocks = (N_NODES + 127) / 128;

    cudaStream_t s2;
    cudaEvent_t ev0, ev1;
    cudaStreamCreateWithFlags(&s2, cudaStreamNonBlocking);
    cudaEventCreateWithFlags(&ev0, cudaEventDisableTiming);
    cudaEventCreateWithFlags(&ev1, cudaEventDisableTiming);

    cudaEventRecord(ev0, 0);
    cudaStreamWaitEvent(s2, ev0, 0);

    // main: GEMM1 — concurrent with CSR chain
    gemm_fused<<<gemmBlocks, TB>>>(x, W1, as1, ad1, 0);

    // s2: CSR build chain
    init_kernel<<<initBlocks, TB, 0, s2>>>();
    hist_kernel<<<histBlocks, TB, 0, s2>>>(ei);
    scan1_kernel<<<NB, SCAN_B, 0, s2>>>();
    scan2_kernel<<<1, 64, 0, s2>>>();
    scan3_kernel<<<nodeBlocks, TB, 0, s2>>>();
    scatter_kernel<<<scatBlocks, TB, 0, s2>>>(ei);
    cudaEventRecord(ev1, s2);

    cudaStreamWaitEvent(0, ev1, 0);                   // join

    gat_agg_kernel<<<warpNodeBlocks, TB>>>(b1, bat, 0, 0);
    gemm_fused<<<gemmBlocks, TB>>>(nullptr, W2, as2, ad2, 1);
    gat_agg_kernel<<<warpNodeBlocks, TB>>>(b2, bat, 1, 1);
    final_kernel<<<(NG * 32 + TB - 1) / TB, TB>>>(fcw, fcb, out);
}